// round 14
// baseline (speedup 1.0000x reference)
#include <cuda_runtime.h>
#include <cuda_bf16.h>
#include <cstdint>
#include <cstddef>

// Problem dims
#define B_  8
#define L_  2048
#define V_  10000
#define E_  512
#define H_  512
#define ML  (B_*L_)     // 16384 flattened rows

// ---------------- scratch (device globals; allocation-free) ----------------
__device__ float g_xproj[(size_t)ML * H_];            // 32 MB
__device__ float g_z[(size_t)ML * H_];                // 32 MB
__device__ float g_attv[(size_t)ML * H_];             // 32 MB
__device__ float g_decin[(size_t)ML * H_];            // 32 MB
__device__ float g_scores[(size_t)B_ * L_ * L_];      // 134 MB (scores -> att in place)

// ---------------- common 128x128x16 fp32 SIMT GEMM core --------------------
#define BKT 16
#define LDW 132   // smem row stride in floats (128 + 4 pad)

__device__ __forceinline__ void store_trans(float* S, int r, int kq, float4 v) {
    S[(kq*4+0)*LDW + r] = v.x;
    S[(kq*4+1)*LDW + r] = v.y;
    S[(kq*4+2)*LDW + r] = v.z;
    S[(kq*4+3)*LDW + r] = v.w;
}

__device__ __forceinline__ void tile_fma(const float* __restrict__ As,
                                         const float* __restrict__ Bs,
                                         float acc[8][8], int tx, int ty) {
#pragma unroll
    for (int kk = 0; kk < BKT; kk++) {
        float4 a0 = *(const float4*)(As + kk*LDW + ty*8);
        float4 a1 = *(const float4*)(As + kk*LDW + ty*8 + 4);
        float4 b0 = *(const float4*)(Bs + kk*LDW + tx*8);
        float4 b1 = *(const float4*)(Bs + kk*LDW + tx*8 + 4);
        float a[8] = {a0.x,a0.y,a0.z,a0.w,a1.x,a1.y,a1.z,a1.w};
        float b[8] = {b0.x,b0.y,b0.z,b0.w,b1.x,b1.y,b1.z,b1.w};
#pragma unroll
        for (int i = 0; i < 8; i++)
#pragma unroll
            for (int j = 0; j < 8; j++)
                acc[i][j] = fmaf(a[i], b[j], acc[i][j]);
    }
}

// ---------------- 1) x_proj = emb[batch] @ W_ih^T + b_ih -------------------
__global__ void __launch_bounds__(256, 2) xproj_kernel(
    const int* __restrict__ batch, const float* __restrict__ emb,
    const float* __restrict__ W_ih, const float* __restrict__ b_ih)
{
    __shared__ float As[BKT*LDW], Bs[BKT*LDW];
    const int m0 = blockIdx.x * 128, n0 = blockIdx.y * 128;
    const int tid = threadIdx.x, tx = tid & 15, ty = tid >> 4;
    const int r0 = tid >> 2, r1 = r0 + 64, kq = tid & 3;

    const float* arow0 = emb + (size_t)batch[m0 + r0] * E_;
    const float* arow1 = emb + (size_t)batch[m0 + r1] * E_;
    const float* brow0 = W_ih + (size_t)(n0 + r0) * E_;
    const float* brow1 = W_ih + (size_t)(n0 + r1) * E_;

    float acc[8][8] = {};
    for (int k0 = 0; k0 < E_; k0 += BKT) {
        float4 a0 = *(const float4*)(arow0 + k0 + kq*4);
        float4 a1 = *(const float4*)(arow1 + k0 + kq*4);
        float4 b0 = *(const float4*)(brow0 + k0 + kq*4);
        float4 b1 = *(const float4*)(brow1 + k0 + kq*4);
        __syncthreads();
        store_trans(As, r0, kq, a0); store_trans(As, r1, kq, a1);
        store_trans(Bs, r0, kq, b0); store_trans(Bs, r1, kq, b1);
        __syncthreads();
        tile_fma(As, Bs, acc, tx, ty);
    }
    float4 bi0 = *(const float4*)(b_ih + n0 + tx*8);
    float4 bi1 = *(const float4*)(b_ih + n0 + tx*8 + 4);
#pragma unroll
    for (int i = 0; i < 8; i++) {
        float* orow = g_xproj + (size_t)(m0 + ty*8 + i) * H_ + n0 + tx*8;
        *(float4*)(orow)   = make_float4(acc[i][0]+bi0.x, acc[i][1]+bi0.y, acc[i][2]+bi0.z, acc[i][3]+bi0.w);
        *(float4*)(orow+4) = make_float4(acc[i][4]+bi1.x, acc[i][5]+bi1.y, acc[i][6]+bi1.z, acc[i][7]+bi1.w);
    }
}

// ---------------- 2) RNN: cluster of 8 CTAs per batch element --------------
// h_new[b,j] = tanh(xp[b,t,j] + sum_i h[b,i]*W_hh[j,i] + b_hh[j])
// Each CTA: 64 outputs j; thread t: j = rank*64 + t/4, k-quarter q = t&3.
// W_hh slice lives in 128 registers/thread; h state double-buffered in SMEM,
// broadcast to all 8 CTAs via st.shared::cluster; barrier.cluster per step.
__device__ __forceinline__ uint32_t ctarank() {
    uint32_t r; asm("mov.u32 %0, %%cluster_ctarank;" : "=r"(r)); return r;
}
#define RNN_CLUSTER_SYNC() do { \
    asm volatile("barrier.cluster.arrive.aligned;" ::: "memory"); \
    asm volatile("barrier.cluster.wait.aligned;"   ::: "memory"); } while (0)

__global__ void __cluster_dims__(8, 1, 1) __launch_bounds__(256, 1)
rnn_kernel(const float* __restrict__ W_hh, const float* __restrict__ b_hh)
{
    __shared__ float h_s[2][H_];
    const int tid  = threadIdx.x;
    const uint32_t rank = ctarank();
    const int b    = blockIdx.x >> 3;
    const int q    = tid & 3;                 // k-quarter (128 k's each)
    const int j    = rank * 64 + (tid >> 2);  // output index 0..511

    // Load W_hh[j][q*128 .. q*128+127] into registers, bank-staggered order.
    float4 Wr[32];
#pragma unroll
    for (int i = 0; i < 32; i++) {
        int f4 = q*32 + ((i + 2*q) & 31);
        Wr[i] = *(const float4*)(W_hh + (size_t)j * H_ + f4 * 4);
    }
    const float bias = b_hh[j];

    for (int idx = tid; idx < 2*H_; idx += 256) ((float*)h_s)[idx] = 0.0f;
    const uint32_t h_base = (uint32_t)__cvta_generic_to_shared(&h_s[0][0]);

    RNN_CLUSTER_SYNC();   // all zero-init visible cluster-wide

    const float* xp_row = g_xproj + (size_t)b * L_ * H_ + j;
    float*       z_row  = g_z     + (size_t)b * L_ * H_ + j;

    int p = 0;
    for (int step = 0; step < L_; step++) {
        float xpv = 0.0f;
        if (q == 0) xpv = xp_row[(size_t)step * H_];   // prefetch early

        const float4* h4 = (const float4*)(p ? h_s[1] : h_s[0]);
        float acc = 0.0f;
#pragma unroll
        for (int i = 0; i < 32; i++) {
            int f4 = q*32 + ((i + 2*q) & 31);          // conflict-free stagger
            float4 hv = h4[f4];
            acc = fmaf(Wr[i].x, hv.x, acc);
            acc = fmaf(Wr[i].y, hv.y, acc);
            acc = fmaf(Wr[i].z, hv.z, acc);
            acc = fmaf(Wr[i].w, hv.w, acc);
        }
        acc += __shfl_xor_sync(0xffffffffu, acc, 1);
        acc += __shfl_xor_sync(0xffffffffu, acc, 2);

        if (q == 0) {
            float hv = tanhf(acc + xpv + bias);
            z_row[(size_t)step * H_] = hv;
            uint32_t dst = h_base + (uint32_t)(((p ^ 1) * H_ + j) * 4);
#pragma unroll
            for (int r = 0; r < 8; r++) {
                uint32_t rad;
                asm volatile("mapa.shared::cluster.u32 %0, %1, %2;"
                             : "=r"(rad) : "r"(dst), "r"(r));
                asm volatile("st.shared::cluster.f32 [%0], %1;"
                             :: "r"(rad), "f"(hv) : "memory");
            }
        }
        RNN_CLUSTER_SYNC();
        p ^= 1;
    }
}

// ---------------- 3) scores = z @ z^T (strict lower triangle only) ---------
__global__ void __launch_bounds__(256, 2) scores_kernel()
{
    const int it = blockIdx.x, jt = blockIdx.y, b = blockIdx.z;
    if (jt > it) return;
    __shared__ float As[BKT*LDW], Bs[BKT*LDW];
    const float* zb = g_z + (size_t)b * L_ * H_;
    const int l0 = it * 128, m0 = jt * 128;
    const int tid = threadIdx.x, tx = tid & 15, ty = tid >> 4;
    const int r0 = tid >> 2, r1 = r0 + 64, kq = tid & 3;

    const float* arow0 = zb + (size_t)(l0 + r0) * H_;
    const float* arow1 = zb + (size_t)(l0 + r1) * H_;
    const float* brow0 = zb + (size_t)(m0 + r0) * H_;
    const float* brow1 = zb + (size_t)(m0 + r1) * H_;

    float acc[8][8] = {};
    for (int k0 = 0; k0 < H_; k0 += BKT) {
        float4 a0 = *(const float4*)(arow0 + k0 + kq*4);
        float4 a1 = *(const float4*)(arow1 + k0 + kq*4);
        float4 b0 = *(const float4*)(brow0 + k0 + kq*4);
        float4 b1 = *(const float4*)(brow1 + k0 + kq*4);
        __syncthreads();
        store_trans(As, r0, kq, a0); store_trans(As, r1, kq, a1);
        store_trans(Bs, r0, kq, b0); store_trans(Bs, r1, kq, b1);
        __syncthreads();
        tile_fma(As, Bs, acc, tx, ty);
    }
    const bool full = (jt < it);
    float* sb = g_scores + (size_t)b * L_ * L_;
#pragma unroll
    for (int i = 0; i < 8; i++) {
        const int gl = l0 + ty*8 + i;
        float* srow = sb + (size_t)gl * L_ + m0 + tx*8;
#pragma unroll
        for (int jj = 0; jj < 8; jj++) {
            const int gm = m0 + tx*8 + jj;
            if (full || gm < gl) srow[jj] = acc[i][jj];
        }
    }
}

// ---------------- 4) softmax rows (in place; att semantics) ----------------
// l==0: uniform 1/L (all entries were -1e9). l>=1: softmax over m<l; 0 for m>=l.
__global__ void __launch_bounds__(256) softmax_kernel()
{
    const int row = blockIdx.x;           // b*L + l
    const int l   = row & (L_ - 1);
    float* s = g_scores + (size_t)row * L_;
    const int tid = threadIdx.x;
    __shared__ float red[256];

    if (l == 0) {
        const float u = 1.0f / (float)L_;
        for (int m = tid; m < L_; m += 256) s[m] = u;
        return;
    }
    float mx = -3.402823466e38f;
    for (int m = tid; m < l; m += 256) mx = fmaxf(mx, s[m]);
    red[tid] = mx; __syncthreads();
    for (int o = 128; o; o >>= 1) {
        if (tid < o) red[tid] = fmaxf(red[tid], red[tid + o]);
        __syncthreads();
    }
    mx = red[0]; __syncthreads();

    float sum = 0.0f;
    for (int m = tid; m < l; m += 256) {
        float e = expf(s[m] - mx);
        s[m] = e;
        sum += e;
    }
    red[tid] = sum; __syncthreads();
    for (int o = 128; o; o >>= 1) {
        if (tid < o) red[tid] += red[tid + o];
        __syncthreads();
    }
    const float inv = 1.0f / red[0];
    for (int m = tid; m < l; m += 256) s[m] *= inv;
    for (int m = l + tid; m < L_; m += 256) s[m] = 0.0f;
}

// ---------------- 5) att_vec = att @ z (NN; per-tile K limit) --------------
__global__ void __launch_bounds__(256, 2) attv_kernel()
{
    const int it = blockIdx.x, nt = blockIdx.y, b = blockIdx.z;
    __shared__ float As[BKT*LDW], Bs[BKT*LDW];
    const int l0 = it * 128, n0 = nt * 128;
    const float* ab = g_scores + (size_t)b * L_ * L_;
    const float* zb = g_z      + (size_t)b * L_ * H_;
    const int tid = threadIdx.x, tx = tid & 15, ty = tid >> 4;
    const int r0 = tid >> 2, r1 = r0 + 64, kq = tid & 3;
    const int kB0 = tid >> 5, kB1 = kB0 + 8, nf4 = tid & 31;

    const float* arow0 = ab + (size_t)(l0 + r0) * L_;
    const float* arow1 = ab + (size_t)(l0 + r1) * L_;
    // tile 0 contains the uniform row 0 -> needs full K; others: k <= tile end
    const int kend = (it == 0) ? L_ : (it + 1) * 128;

    float acc[8][8] = {};
    for (int k0 = 0; k0 < kend; k0 += BKT) {
        float4 a0 = *(const float4*)(arow0 + k0 + kq*4);
        float4 a1 = *(const float4*)(arow1 + k0 + kq*4);
        float4 b0 = *(const float4*)(zb + (size_t)(k0 + kB0) * H_ + n0 + nf4*4);
        float4 b1 = *(const float4*)(zb + (size_t)(k0 + kB1) * H_ + n0 + nf4*4);
        __syncthreads();
        store_trans(As, r0, kq, a0); store_trans(As, r1, kq, a1);
        *(float4*)(Bs + kB0*LDW + nf4*4) = b0;
        *(float4*)(Bs + kB1*LDW + nf4*4) = b1;
        __syncthreads();
        tile_fma(As, Bs, acc, tx, ty);
    }
#pragma unroll
    for (int i = 0; i < 8; i++) {
        float* orow = g_attv + ((size_t)b * L_ + l0 + ty*8 + i) * H_ + n0 + tx*8;
        *(float4*)(orow)   = make_float4(acc[i][0], acc[i][1], acc[i][2], acc[i][3]);
        *(float4*)(orow+4) = make_float4(acc[i][4], acc[i][5], acc[i][6], acc[i][7]);
    }
}

// ---------------- 6) dec_in = [att_vec, z] @ W_c^T + b_c -------------------
__global__ void __launch_bounds__(256, 2) decin_kernel(
    const float* __restrict__ W_c, const float* __restrict__ b_c)
{
    __shared__ float As[BKT*LDW], Bs[BKT*LDW];
    const int m0 = blockIdx.x * 128, n0 = blockIdx.y * 128;
    const int tid = threadIdx.x, tx = tid & 15, ty = tid >> 4;
    const int r0 = tid >> 2, r1 = r0 + 64, kq = tid & 3;

    const float* a0att = g_attv + (size_t)(m0 + r0) * H_;
    const float* a1att = g_attv + (size_t)(m0 + r1) * H_;
    const float* a0z   = g_z    + (size_t)(m0 + r0) * H_;
    const float* a1z   = g_z    + (size_t)(m0 + r1) * H_;
    const float* brow0 = W_c + (size_t)(n0 + r0) * (2*H_);
    const float* brow1 = W_c + (size_t)(n0 + r1) * (2*H_);

    float acc[8][8] = {};
    for (int k0 = 0; k0 < 2*H_; k0 += BKT) {
        const float* s0 = (k0 < H_) ? (a0att + k0) : (a0z + k0 - H_);
        const float* s1 = (k0 < H_) ? (a1att + k0) : (a1z + k0 - H_);
        float4 a0 = *(const float4*)(s0 + kq*4);
        float4 a1 = *(const float4*)(s1 + kq*4);
        float4 b0 = *(const float4*)(brow0 + k0 + kq*4);
        float4 b1 = *(const float4*)(brow1 + k0 + kq*4);
        __syncthreads();
        store_trans(As, r0, kq, a0); store_trans(As, r1, kq, a1);
        store_trans(Bs, r0, kq, b0); store_trans(Bs, r1, kq, b1);
        __syncthreads();
        tile_fma(As, Bs, acc, tx, ty);
    }
    float4 bc0 = *(const float4*)(b_c + n0 + tx*8);
    float4 bc1 = *(const float4*)(b_c + n0 + tx*8 + 4);
#pragma unroll
    for (int i = 0; i < 8; i++) {
        float* orow = g_decin + (size_t)(m0 + ty*8 + i) * H_ + n0 + tx*8;
        *(float4*)(orow)   = make_float4(acc[i][0]+bc0.x, acc[i][1]+bc0.y, acc[i][2]+bc0.z, acc[i][3]+bc0.w);
        *(float4*)(orow+4) = make_float4(acc[i][4]+bc1.x, acc[i][5]+bc1.y, acc[i][6]+bc1.z, acc[i][7]+bc1.w);
    }
}

// ---------------- 7) logits = dec_in @ W_d^T + b_d -------------------------
__global__ void __launch_bounds__(256, 2) logits_kernel(
    const float* __restrict__ W_d, const float* __restrict__ b_d,
    float* __restrict__ out)
{
    __shared__ float As[BKT*LDW], Bs[BKT*LDW];
    const int m0 = blockIdx.x * 128, n0 = blockIdx.y * 128;
    const int tid = threadIdx.x, tx = tid & 15, ty = tid >> 4;
    const int r0 = tid >> 2, r1 = r0 + 64, kq = tid & 3;

    const float* arow0 = g_decin + (size_t)(m0 + r0) * H_;
    const float* arow1 = g_decin + (size_t)(m0 + r1) * H_;
    const int nrow0 = n0 + r0, nrow1 = n0 + r1;
    const bool v0 = nrow0 < V_, v1 = nrow1 < V_;
    const float* brow0 = W_d + (size_t)(v0 ? nrow0 : 0) * H_;
    const float* brow1 = W_d + (size_t)(v1 ? nrow1 : 0) * H_;

    float acc[8][8] = {};
    for (int k0 = 0; k0 < H_; k0 += BKT) {
        float4 a0 = *(const float4*)(arow0 + k0 + kq*4);
        float4 a1 = *(const float4*)(arow1 + k0 + kq*4);
        float4 b0 = make_float4(0.f,0.f,0.f,0.f), b1 = b0;
        if (v0) b0 = *(const float4*)(brow0 + k0 + kq*4);
        if (v1) b1 = *(const float4*)(brow1 + k0 + kq*4);
        __syncthreads();
        store_trans(As, r0, kq, a0); store_trans(As, r1, kq, a1);
        store_trans(Bs, r0, kq, b0); store_trans(Bs, r1, kq, b1);
        __syncthreads();
        tile_fma(As, Bs, acc, tx, ty);
    }
    const int gn = n0 + tx*8;          // V_ % 8 == 0 -> whole 8-group in/out
    if (gn < V_) {
        float4 bd0 = *(const float4*)(b_d + gn);
        float4 bd1 = *(const float4*)(b_d + gn + 4);
#pragma unroll
        for (int i = 0; i < 8; i++) {
            float* orow = out + (size_t)(m0 + ty*8 + i) * V_ + gn;
            *(float4*)(orow)   = make_float4(acc[i][0]+bd0.x, acc[i][1]+bd0.y, acc[i][2]+bd0.z, acc[i][3]+bd0.w);
            *(float4*)(orow+4) = make_float4(acc[i][4]+bd1.x, acc[i][5]+bd1.y, acc[i][6]+bd1.z, acc[i][7]+bd1.w);
        }
    }
}

// ---------------- launch ----------------------------------------------------
extern "C" void kernel_launch(void* const* d_in, const int* in_sizes, int n_in,
                              void* d_out, int out_size)
{
    const int*   batch = (const int*)  d_in[0];
    const float* emb   = (const float*)d_in[1];
    const float* W_ih  = (const float*)d_in[2];
    const float* b_ih  = (const float*)d_in[3];
    const float* W_hh  = (const float*)d_in[4];
    const float* b_hh  = (const float*)d_in[5];
    const float* W_c   = (const float*)d_in[6];
    const float* b_c   = (const float*)d_in[7];
    const float* W_d   = (const float*)d_in[8];
    const float* b_d   = (const float*)d_in[9];
    float* out = (float*)d_out;
    (void)in_sizes; (void)n_in; (void)out_size;

    xproj_kernel  <<<dim3(ML/128, H_/128), 256>>>(batch, emb, W_ih, b_ih);
    rnn_kernel    <<<dim3(B_*8), 256>>>(W_hh, b_hh);           // 8 clusters of 8 CTAs
    scores_kernel <<<dim3(L_/128, L_/128, B_), 256>>>();
    softmax_kernel<<<dim3(ML), 256>>>();
    attv_kernel   <<<dim3(L_/128, H_/128, B_), 256>>>();
    decin_kernel  <<<dim3(ML/128, H_/128), 256>>>(W_c, b_c);
    logits_kernel <<<dim3(ML/128, (V_ + 127)/128), 256>>>(W_d, b_d, out);
}

// round 15
// speedup vs baseline: 1.0171x; 1.0171x over previous
#include <cuda_runtime.h>
#include <cuda_bf16.h>
#include <cstdint>
#include <cstddef>

// Problem dims
#define B_  8
#define L_  2048
#define V_  10000
#define E_  512
#define H_  512
#define ML  (B_*L_)     // 16384 flattened rows

// ---------------- scratch (device globals; allocation-free) ----------------
__device__ float g_xproj[(size_t)ML * H_];            // 32 MB
__device__ float g_z[(size_t)ML * H_];                // 32 MB
__device__ float g_attv[(size_t)ML * H_];             // 32 MB
__device__ float g_decin[(size_t)ML * H_];            // 32 MB
__device__ float g_scores[(size_t)B_ * L_ * L_];      // 134 MB (scores -> att in place)

// ---------------- packed f32x2 helpers --------------------------------------
__device__ __forceinline__ void ffma2(unsigned long long& c,
                                      unsigned long long a,
                                      unsigned long long b) {
    asm("fma.rn.f32x2 %0, %1, %2, %0;" : "+l"(c) : "l"(a), "l"(b));
}
__device__ __forceinline__ unsigned long long dup2(float v) {
    unsigned long long d; unsigned int r = __float_as_uint(v);
    asm("mov.b64 %0, {%1, %1};" : "=l"(d) : "r"(r));
    return d;
}
__device__ __forceinline__ void unpk(unsigned long long p, float& lo, float& hi) {
    unsigned int l, h;
    asm("mov.b64 {%0, %1}, %2;" : "=r"(l), "=r"(h) : "l"(p));
    lo = __uint_as_float(l); hi = __uint_as_float(h);
}

// ---------------- common 128x128x16 fp32x2 SIMT GEMM core -------------------
#define BKT 16
#define LDW 132   // smem row stride in floats (128 + 4 pad)

__device__ __forceinline__ void store_trans(float* S, int r, int kq, float4 v) {
    S[(kq*4+0)*LDW + r] = v.x;
    S[(kq*4+1)*LDW + r] = v.y;
    S[(kq*4+2)*LDW + r] = v.z;
    S[(kq*4+3)*LDW + r] = v.w;
}

// acc2[i][jp] packs (acc[i][2jp], acc[i][2jp+1]) as f32x2
__device__ __forceinline__ void tile_fma(const float* __restrict__ As,
                                         const float* __restrict__ Bs,
                                         unsigned long long acc2[8][4],
                                         int tx, int ty) {
#pragma unroll
    for (int kk = 0; kk < BKT; kk++) {
        float4 a0 = *(const float4*)(As + kk*LDW + ty*8);
        float4 a1 = *(const float4*)(As + kk*LDW + ty*8 + 4);
        ulonglong2 bq0 = *(const ulonglong2*)(Bs + kk*LDW + tx*8);
        ulonglong2 bq1 = *(const ulonglong2*)(Bs + kk*LDW + tx*8 + 4);
        unsigned long long bp[4] = {bq0.x, bq0.y, bq1.x, bq1.y};
        float a[8] = {a0.x,a0.y,a0.z,a0.w,a1.x,a1.y,a1.z,a1.w};
#pragma unroll
        for (int i = 0; i < 8; i++) {
            unsigned long long ad = dup2(a[i]);
#pragma unroll
            for (int jp = 0; jp < 4; jp++) ffma2(acc2[i][jp], ad, bp[jp]);
        }
    }
}

__device__ __forceinline__ void unpack_acc(const unsigned long long acc2[8][4],
                                           float acc[8][8]) {
#pragma unroll
    for (int i = 0; i < 8; i++)
#pragma unroll
        for (int jp = 0; jp < 4; jp++)
            unpk(acc2[i][jp], acc[i][2*jp], acc[i][2*jp+1]);
}

// ---------------- 1) x_proj = emb[batch] @ W_ih^T + b_ih -------------------
__global__ void __launch_bounds__(256, 2) xproj_kernel(
    const int* __restrict__ batch, const float* __restrict__ emb,
    const float* __restrict__ W_ih, const float* __restrict__ b_ih)
{
    __shared__ __align__(16) float As[BKT*LDW], Bs[BKT*LDW];
    const int m0 = blockIdx.x * 128, n0 = blockIdx.y * 128;
    const int tid = threadIdx.x, tx = tid & 15, ty = tid >> 4;
    const int r0 = tid >> 2, r1 = r0 + 64, kq = tid & 3;

    const float* arow0 = emb + (size_t)batch[m0 + r0] * E_;
    const float* arow1 = emb + (size_t)batch[m0 + r1] * E_;
    const float* brow0 = W_ih + (size_t)(n0 + r0) * E_;
    const float* brow1 = W_ih + (size_t)(n0 + r1) * E_;

    float4 a0 = *(const float4*)(arow0 + kq*4);
    float4 a1 = *(const float4*)(arow1 + kq*4);
    float4 b0 = *(const float4*)(brow0 + kq*4);
    float4 b1 = *(const float4*)(brow1 + kq*4);

    unsigned long long acc2[8][4] = {};
    for (int k0 = 0; k0 < E_; k0 += BKT) {
        __syncthreads();
        store_trans(As, r0, kq, a0); store_trans(As, r1, kq, a1);
        store_trans(Bs, r0, kq, b0); store_trans(Bs, r1, kq, b1);
        __syncthreads();
        if (k0 + BKT < E_) {          // prefetch next k-tile (overlaps FMA)
            a0 = *(const float4*)(arow0 + k0 + BKT + kq*4);
            a1 = *(const float4*)(arow1 + k0 + BKT + kq*4);
            b0 = *(const float4*)(brow0 + k0 + BKT + kq*4);
            b1 = *(const float4*)(brow1 + k0 + BKT + kq*4);
        }
        tile_fma(As, Bs, acc2, tx, ty);
    }
    float acc[8][8]; unpack_acc(acc2, acc);
    float4 bi0 = *(const float4*)(b_ih + n0 + tx*8);
    float4 bi1 = *(const float4*)(b_ih + n0 + tx*8 + 4);
#pragma unroll
    for (int i = 0; i < 8; i++) {
        float* orow = g_xproj + (size_t)(m0 + ty*8 + i) * H_ + n0 + tx*8;
        *(float4*)(orow)   = make_float4(acc[i][0]+bi0.x, acc[i][1]+bi0.y, acc[i][2]+bi0.z, acc[i][3]+bi0.w);
        *(float4*)(orow+4) = make_float4(acc[i][4]+bi1.x, acc[i][5]+bi1.y, acc[i][6]+bi1.z, acc[i][7]+bi1.w);
    }
}

// ---------------- 2) RNN: cluster of 8 CTAs per batch element --------------
__device__ __forceinline__ uint32_t ctarank() {
    uint32_t r; asm("mov.u32 %0, %%cluster_ctarank;" : "=r"(r)); return r;
}
#define RNN_CLUSTER_SYNC() do { \
    asm volatile("barrier.cluster.arrive.aligned;" ::: "memory"); \
    asm volatile("barrier.cluster.wait.aligned;"   ::: "memory"); } while (0)

__global__ void __cluster_dims__(8, 1, 1) __launch_bounds__(256, 1)
rnn_kernel(const float* __restrict__ W_hh, const float* __restrict__ b_hh)
{
    __shared__ __align__(16) float h_s[2][H_];
    const int tid  = threadIdx.x;
    const uint32_t rank = ctarank();
    const int b    = blockIdx.x >> 3;
    const int q    = tid & 3;                 // k-quarter (128 k's each)
    const int j    = rank * 64 + (tid >> 2);  // output index 0..511

    // W_hh[j][q*128 .. q*128+127] as 64 packed f32x2 pairs, bank-staggered.
    unsigned long long Wp[64];
#pragma unroll
    for (int i = 0; i < 32; i++) {
        int f4 = q*32 + ((i + 2*q) & 31);
        ulonglong2 w2 = *(const ulonglong2*)(W_hh + (size_t)j * H_ + f4 * 4);
        Wp[2*i]   = w2.x;
        Wp[2*i+1] = w2.y;
    }
    const float bias = b_hh[j];

    for (int idx = tid; idx < 2*H_; idx += 256) ((float*)h_s)[idx] = 0.0f;
    const uint32_t h_base = (uint32_t)__cvta_generic_to_shared(&h_s[0][0]);

    RNN_CLUSTER_SYNC();   // all zero-init visible cluster-wide

    const float* xp_row = g_xproj + (size_t)b * L_ * H_ + j;
    float*       z_row  = g_z     + (size_t)b * L_ * H_ + j;

    int p = 0;
    for (int step = 0; step < L_; step++) {
        float xpv = 0.0f;
        if (q == 0) xpv = xp_row[(size_t)step * H_];   // prefetch early

        const float* hb = p ? h_s[1] : h_s[0];
        unsigned long long c0 = 0ull, c1 = 0ull, c2 = 0ull, c3 = 0ull;
#pragma unroll
        for (int i = 0; i < 32; i += 4) {
            int f40 = q*32 + ((i + 0 + 2*q) & 31);
            int f41 = q*32 + ((i + 1 + 2*q) & 31);
            int f42 = q*32 + ((i + 2 + 2*q) & 31);
            int f43 = q*32 + ((i + 3 + 2*q) & 31);
            ulonglong2 h0 = *(const ulonglong2*)(hb + f40*4);
            ulonglong2 h1 = *(const ulonglong2*)(hb + f41*4);
            ulonglong2 h2 = *(const ulonglong2*)(hb + f42*4);
            ulonglong2 h3 = *(const ulonglong2*)(hb + f43*4);
            ffma2(c0, Wp[2*(i+0)], h0.x); ffma2(c0, Wp[2*(i+0)+1], h0.y);
            ffma2(c1, Wp[2*(i+1)], h1.x); ffma2(c1, Wp[2*(i+1)+1], h1.y);
            ffma2(c2, Wp[2*(i+2)], h2.x); ffma2(c2, Wp[2*(i+2)+1], h2.y);
            ffma2(c3, Wp[2*(i+3)], h3.x); ffma2(c3, Wp[2*(i+3)+1], h3.y);
        }
        float l0,h0f,l1,h1f,l2,h2f,l3,h3f;
        unpk(c0,l0,h0f); unpk(c1,l1,h1f); unpk(c2,l2,h2f); unpk(c3,l3,h3f);
        float acc = ((l0+h0f)+(l1+h1f)) + ((l2+h2f)+(l3+h3f));
        acc += __shfl_xor_sync(0xffffffffu, acc, 1);
        acc += __shfl_xor_sync(0xffffffffu, acc, 2);

        if (q == 0) {
            float hv = tanhf(acc + xpv + bias);
            z_row[(size_t)step * H_] = hv;
            uint32_t dst = h_base + (uint32_t)(((p ^ 1) * H_ + j) * 4);
#pragma unroll
            for (int r = 0; r < 8; r++) {
                uint32_t rad;
                asm volatile("mapa.shared::cluster.u32 %0, %1, %2;"
                             : "=r"(rad) : "r"(dst), "r"(r));
                asm volatile("st.shared::cluster.f32 [%0], %1;"
                             :: "r"(rad), "f"(hv) : "memory");
            }
        }
        RNN_CLUSTER_SYNC();
        p ^= 1;
    }
}

// ---------------- 3) scores = z @ z^T (strict lower triangle only) ---------
__global__ void __launch_bounds__(256, 2) scores_kernel()
{
    const int it = blockIdx.x, jt = blockIdx.y, b = blockIdx.z;
    if (jt > it) return;
    __shared__ __align__(16) float As[BKT*LDW], Bs[BKT*LDW];
    const float* zb = g_z + (size_t)b * L_ * H_;
    const int l0 = it * 128, m0 = jt * 128;
    const int tid = threadIdx.x, tx = tid & 15, ty = tid >> 4;
    const int r0 = tid >> 2, r1 = r0 + 64, kq = tid & 3;

    const float* arow0 = zb + (size_t)(l0 + r0) * H_;
    const float* arow1 = zb + (size_t)(l0 + r1) * H_;
    const float* brow0 = zb + (size_t)(m0 + r0) * H_;
    const float* brow1 = zb + (size_t)(m0 + r1) * H_;

    float4 a0 = *(const float4*)(arow0 + kq*4);
    float4 a1 = *(const float4*)(arow1 + kq*4);
    float4 b0 = *(const float4*)(brow0 + kq*4);
    float4 b1 = *(const float4*)(brow1 + kq*4);

    unsigned long long acc2[8][4] = {};
    for (int k0 = 0; k0 < H_; k0 += BKT) {
        __syncthreads();
        store_trans(As, r0, kq, a0); store_trans(As, r1, kq, a1);
        store_trans(Bs, r0, kq, b0); store_trans(Bs, r1, kq, b1);
        __syncthreads();
        if (k0 + BKT < H_) {
            a0 = *(const float4*)(arow0 + k0 + BKT + kq*4);
            a1 = *(const float4*)(arow1 + k0 + BKT + kq*4);
            b0 = *(const float4*)(brow0 + k0 + BKT + kq*4);
            b1 = *(const float4*)(brow1 + k0 + BKT + kq*4);
        }
        tile_fma(As, Bs, acc2, tx, ty);
    }
    float acc[8][8]; unpack_acc(acc2, acc);
    const bool full = (jt < it);
    float* sb = g_scores + (size_t)b * L_ * L_;
#pragma unroll
    for (int i = 0; i < 8; i++) {
        const int gl = l0 + ty*8 + i;
        float* srow = sb + (size_t)gl * L_ + m0 + tx*8;
#pragma unroll
        for (int jj = 0; jj < 8; jj++) {
            const int gm = m0 + tx*8 + jj;
            if (full || gm < gl) srow[jj] = acc[i][jj];
        }
    }
}

// ---------------- 4) softmax rows (in place; att semantics) ----------------
__global__ void __launch_bounds__(256) softmax_kernel()
{
    const int row = blockIdx.x;           // b*L + l
    const int l   = row & (L_ - 1);
    float* s = g_scores + (size_t)row * L_;
    const int tid = threadIdx.x;
    __shared__ float red[256];

    if (l == 0) {
        const float u = 1.0f / (float)L_;
        for (int m = tid; m < L_; m += 256) s[m] = u;
        return;
    }
    float mx = -3.402823466e38f;
    for (int m = tid; m < l; m += 256) mx = fmaxf(mx, s[m]);
    red[tid] = mx; __syncthreads();
    for (int o = 128; o; o >>= 1) {
        if (tid < o) red[tid] = fmaxf(red[tid], red[tid + o]);
        __syncthreads();
    }
    mx = red[0]; __syncthreads();

    float sum = 0.0f;
    for (int m = tid; m < l; m += 256) {
        float e = expf(s[m] - mx);
        s[m] = e;
        sum += e;
    }
    red[tid] = sum; __syncthreads();
    for (int o = 128; o; o >>= 1) {
        if (tid < o) red[tid] += red[tid + o];
        __syncthreads();
    }
    const float inv = 1.0f / red[0];
    for (int m = tid; m < l; m += 256) s[m] *= inv;
    for (int m = l + tid; m < L_; m += 256) s[m] = 0.0f;
}

// ---------------- 5) att_vec = att @ z (NN; per-tile K limit) --------------
__global__ void __launch_bounds__(256, 2) attv_kernel()
{
    const int it = blockIdx.x, nt = blockIdx.y, b = blockIdx.z;
    __shared__ __align__(16) float As[BKT*LDW], Bs[BKT*LDW];
    const int l0 = it * 128, n0 = nt * 128;
    const float* ab = g_scores + (size_t)b * L_ * L_;
    const float* zb = g_z      + (size_t)b * L_ * H_;
    const int tid = threadIdx.x, tx = tid & 15, ty = tid >> 4;
    const int r0 = tid >> 2, r1 = r0 + 64, kq = tid & 3;
    const int kB0 = tid >> 5, kB1 = kB0 + 8, nf4 = tid & 31;

    const float* arow0 = ab + (size_t)(l0 + r0) * L_;
    const float* arow1 = ab + (size_t)(l0 + r1) * L_;
    // tile 0 contains the uniform row 0 -> needs full K; others: k <= tile end
    const int kend = (it == 0) ? L_ : (it + 1) * 128;

    float4 a0 = *(const float4*)(arow0 + kq*4);
    float4 a1 = *(const float4*)(arow1 + kq*4);
    float4 b0 = *(const float4*)(zb + (size_t)kB0 * H_ + n0 + nf4*4);
    float4 b1 = *(const float4*)(zb + (size_t)kB1 * H_ + n0 + nf4*4);

    unsigned long long acc2[8][4] = {};
    for (int k0 = 0; k0 < kend; k0 += BKT) {
        __syncthreads();
        store_trans(As, r0, kq, a0); store_trans(As, r1, kq, a1);
        *(float4*)(Bs + kB0*LDW + nf4*4) = b0;
        *(float4*)(Bs + kB1*LDW + nf4*4) = b1;
        __syncthreads();
        if (k0 + BKT < kend) {
            a0 = *(const float4*)(arow0 + k0 + BKT + kq*4);
            a1 = *(const float4*)(arow1 + k0 + BKT + kq*4);
            b0 = *(const float4*)(zb + (size_t)(k0 + BKT + kB0) * H_ + n0 + nf4*4);
            b1 = *(const float4*)(zb + (size_t)(k0 + BKT + kB1) * H_ + n0 + nf4*4);
        }
        tile_fma(As, Bs, acc2, tx, ty);
    }
    float acc[8][8]; unpack_acc(acc2, acc);
#pragma unroll
    for (int i = 0; i < 8; i++) {
        float* orow = g_attv + ((size_t)b * L_ + l0 + ty*8 + i) * H_ + n0 + tx*8;
        *(float4*)(orow)   = make_float4(acc[i][0], acc[i][1], acc[i][2], acc[i][3]);
        *(float4*)(orow+4) = make_float4(acc[i][4], acc[i][5], acc[i][6], acc[i][7]);
    }
}

// ---------------- 6) dec_in = [att_vec, z] @ W_c^T + b_c -------------------
__global__ void __launch_bounds__(256, 2) decin_kernel(
    const float* __restrict__ W_c, const float* __restrict__ b_c)
{
    __shared__ __align__(16) float As[BKT*LDW], Bs[BKT*LDW];
    const int m0 = blockIdx.x * 128, n0 = blockIdx.y * 128;
    const int tid = threadIdx.x, tx = tid & 15, ty = tid >> 4;
    const int r0 = tid >> 2, r1 = r0 + 64, kq = tid & 3;

    const float* a0att = g_attv + (size_t)(m0 + r0) * H_;
    const float* a1att = g_attv + (size_t)(m0 + r1) * H_;
    const float* a0z   = g_z    + (size_t)(m0 + r0) * H_;
    const float* a1z   = g_z    + (size_t)(m0 + r1) * H_;
    const float* brow0 = W_c + (size_t)(n0 + r0) * (2*H_);
    const float* brow1 = W_c + (size_t)(n0 + r1) * (2*H_);

    float4 a0 = *(const float4*)(a0att + kq*4);
    float4 a1 = *(const float4*)(a1att + kq*4);
    float4 b0 = *(const float4*)(brow0 + kq*4);
    float4 b1 = *(const float4*)(brow1 + kq*4);

    unsigned long long acc2[8][4] = {};
    for (int k0 = 0; k0 < 2*H_; k0 += BKT) {
        __syncthreads();
        store_trans(As, r0, kq, a0); store_trans(As, r1, kq, a1);
        store_trans(Bs, r0, kq, b0); store_trans(Bs, r1, kq, b1);
        __syncthreads();
        const int kn = k0 + BKT;
        if (kn < 2*H_) {
            const float* s0 = (kn < H_) ? (a0att + kn) : (a0z + kn - H_);
            const float* s1 = (kn < H_) ? (a1att + kn) : (a1z + kn - H_);
            a0 = *(const float4*)(s0 + kq*4);
            a1 = *(const float4*)(s1 + kq*4);
            b0 = *(const float4*)(brow0 + kn + kq*4);
            b1 = *(const float4*)(brow1 + kn + kq*4);
        }
        tile_fma(As, Bs, acc2, tx, ty);
    }
    float acc[8][8]; unpack_acc(acc2, acc);
    float4 bc0 = *(const float4*)(b_c + n0 + tx*8);
    float4 bc1 = *(const float4*)(b_c + n0 + tx*8 + 4);
#pragma unroll
    for (int i = 0; i < 8; i++) {
        float* orow = g_decin + (size_t)(m0 + ty*8 + i) * H_ + n0 + tx*8;
        *(float4*)(orow)   = make_float4(acc[i][0]+bc0.x, acc[i][1]+bc0.y, acc[i][2]+bc0.z, acc[i][3]+bc0.w);
        *(float4*)(orow+4) = make_float4(acc[i][4]+bc1.x, acc[i][5]+bc1.y, acc[i][6]+bc1.z, acc[i][7]+bc1.w);
    }
}

// ---------------- 7) logits = dec_in @ W_d^T + b_d -------------------------
__global__ void __launch_bounds__(256, 2) logits_kernel(
    const float* __restrict__ W_d, const float* __restrict__ b_d,
    float* __restrict__ out)
{
    __shared__ __align__(16) float As[BKT*LDW], Bs[BKT*LDW];
    const int m0 = blockIdx.x * 128, n0 = blockIdx.y * 128;
    const int tid = threadIdx.x, tx = tid & 15, ty = tid >> 4;
    const int r0 = tid >> 2, r1 = r0 + 64, kq = tid & 3;

    const float* arow0 = g_decin + (size_t)(m0 + r0) * H_;
    const float* arow1 = g_decin + (size_t)(m0 + r1) * H_;
    const int nrow0 = n0 + r0, nrow1 = n0 + r1;
    const bool v0 = nrow0 < V_, v1 = nrow1 < V_;
    const float* brow0 = W_d + (size_t)(v0 ? nrow0 : 0) * H_;
    const float* brow1 = W_d + (size_t)(v1 ? nrow1 : 0) * H_;

    float4 a0 = *(const float4*)(arow0 + kq*4);
    float4 a1 = *(const float4*)(arow1 + kq*4);
    float4 b0 = make_float4(0.f,0.f,0.f,0.f), b1 = b0;
    if (v0) b0 = *(const float4*)(brow0 + kq*4);
    if (v1) b1 = *(const float4*)(brow1 + kq*4);

    unsigned long long acc2[8][4] = {};
    for (int k0 = 0; k0 < H_; k0 += BKT) {
        __syncthreads();
        store_trans(As, r0, kq, a0); store_trans(As, r1, kq, a1);
        store_trans(Bs, r0, kq, b0); store_trans(Bs, r1, kq, b1);
        __syncthreads();
        if (k0 + BKT < H_) {
            a0 = *(const float4*)(arow0 + k0 + BKT + kq*4);
            a1 = *(const float4*)(arow1 + k0 + BKT + kq*4);
            if (v0) b0 = *(const float4*)(brow0 + k0 + BKT + kq*4);
            if (v1) b1 = *(const float4*)(brow1 + k0 + BKT + kq*4);
        }
        tile_fma(As, Bs, acc2, tx, ty);
    }
    float acc[8][8]; unpack_acc(acc2, acc);
    const int gn = n0 + tx*8;          // V_ % 8 == 0 -> whole 8-group in/out
    if (gn < V_) {
        float4 bd0 = *(const float4*)(b_d + gn);
        float4 bd1 = *(const float4*)(b_d + gn + 4);
#pragma unroll
        for (int i = 0; i < 8; i++) {
            float* orow = out + (size_t)(m0 + ty*8 + i) * V_ + gn;
            *(float4*)(orow)   = make_float4(acc[i][0]+bd0.x, acc[i][1]+bd0.y, acc[i][2]+bd0.z, acc[i][3]+bd0.w);
            *(float4*)(orow+4) = make_float4(acc[i][4]+bd1.x, acc[i][5]+bd1.y, acc[i][6]+bd1.z, acc[i][7]+bd1.w);
        }
    }
}

// ---------------- launch ----------------------------------------------------
extern "C" void kernel_launch(void* const* d_in, const int* in_sizes, int n_in,
                              void* d_out, int out_size)
{
    const int*   batch = (const int*)  d_in[0];
    const float* emb   = (const float*)d_in[1];
    const float* W_ih  = (const float*)d_in[2];
    const float* b_ih  = (const float*)d_in[3];
    const float* W_hh  = (const float*)d_in[4];
    const float* b_hh  = (const float*)d_in[5];
    const float* W_c   = (const float*)d_in[6];
    const float* b_c   = (const float*)d_in[7];
    const float* W_d   = (const float*)d_in[8];
    const float* b_d   = (const float*)d_in[9];
    float* out = (float*)d_out;
    (void)in_sizes; (void)n_in; (void)out_size;

    xproj_kernel  <<<dim3(ML/128, H_/128), 256>>>(batch, emb, W_ih, b_ih);
    rnn_kernel    <<<dim3(B_*8), 256>>>(W_hh, b_hh);           // 8 clusters of 8 CTAs
    scores_kernel <<<dim3(L_/128, L_/128, B_), 256>>>();
    softmax_kernel<<<dim3(ML), 256>>>();
    attv_kernel   <<<dim3(L_/128, H_/128, B_), 256>>>();
    decin_kernel  <<<dim3(ML/128, H_/128), 256>>>(W_c, b_c);
    logits_kernel <<<dim3(ML/128, (V_ + 127)/128), 256>>>(W_d, b_d, out);
}

// round 16
// speedup vs baseline: 1.5890x; 1.5622x over previous
#include <cuda_runtime.h>
#include <cuda_bf16.h>
#include <cstdint>
#include <cstddef>

// Problem dims
#define B_  8
#define L_  2048
#define V_  10000
#define E_  512
#define H_  512
#define ML  (B_*L_)     // 16384 flattened rows

// ---------------- scratch (device globals; allocation-free) ----------------
__device__ float g_xproj[(size_t)ML * H_];            // 32 MB
__device__ float g_z[(size_t)ML * H_];                // 32 MB
__device__ float g_zT[(size_t)B_ * H_ * L_];          // 32 MB  (z transposed per batch)
__device__ float g_attv[(size_t)ML * H_];             // 32 MB
__device__ float g_decin[(size_t)ML * H_];            // 32 MB
__device__ float g_scores[(size_t)B_ * L_ * L_];      // 134 MB (scores -> att in place)

// ---------------- packed f32x2 helpers (RNN only) ---------------------------
__device__ __forceinline__ void ffma2(unsigned long long& c,
                                      unsigned long long a,
                                      unsigned long long b) {
    asm("fma.rn.f32x2 %0, %1, %2, %0;" : "+l"(c) : "l"(a), "l"(b));
}
__device__ __forceinline__ void unpk(unsigned long long p, float& lo, float& hi) {
    unsigned int l, h;
    asm("mov.b64 {%0, %1}, %2;" : "=r"(l), "=r"(h) : "l"(p));
    lo = __uint_as_float(l); hi = __uint_as_float(h);
}

// ======================= bf16x3 tensor-core GEMM core =======================
// CTA: 256 threads (8 warps), tile 128(M) x 128(N), K-step 16 (fp32).
// A tile in smem: row-major [128][16] bf16, row stride 24 halves (48B) -> the
// 8 row-addresses of each ldmatrix phase hit disjoint bank groups.
// B tile in smem: [n][k] (col-major KxN) same layout.
// Each fp32 operand is split hi=bf16(v), lo=bf16(v-hi); D += Ah*Bh + Ah*Bl + Al*Bh.
#define RS 24   // smem row stride in halves (48 bytes)

struct SmemT {
    __nv_bfloat16 Ah[128*RS];
    __nv_bfloat16 Al[128*RS];
    __nv_bfloat16 Bh[128*RS];
    __nv_bfloat16 Bl[128*RS];
};
#define LO_OFF 6144   // bytes from Ah->Al and Bh->Bl (128*24*2)

__device__ __forceinline__ void ldm_x4(uint32_t (&r)[4], uint32_t addr) {
    asm volatile("ldmatrix.sync.aligned.m8n8.x4.shared.b16 {%0,%1,%2,%3}, [%4];"
                 : "=r"(r[0]), "=r"(r[1]), "=r"(r[2]), "=r"(r[3]) : "r"(addr));
}
__device__ __forceinline__ void mma_bf16(float (&c)[4], const uint32_t (&a)[4],
                                         const uint32_t b0, const uint32_t b1) {
    asm volatile(
        "mma.sync.aligned.m16n8k16.row.col.f32.bf16.bf16.f32 "
        "{%0,%1,%2,%3}, {%4,%5,%6,%7}, {%8,%9}, {%0,%1,%2,%3};"
        : "+f"(c[0]), "+f"(c[1]), "+f"(c[2]), "+f"(c[3])
        : "r"(a[0]), "r"(a[1]), "r"(a[2]), "r"(a[3]), "r"(b0), "r"(b1));
}

__device__ __forceinline__ void cvt_split_store(__nv_bfloat16* hp,
                                                __nv_bfloat16* lp, float4 v) {
    __nv_bfloat162 h0 = __floats2bfloat162_rn(v.x, v.y);
    __nv_bfloat162 h1 = __floats2bfloat162_rn(v.z, v.w);
    float2 f0 = __bfloat1622float2(h0);
    float2 f1 = __bfloat1622float2(h1);
    __nv_bfloat162 l0 = __floats2bfloat162_rn(v.x - f0.x, v.y - f0.y);
    __nv_bfloat162 l1 = __floats2bfloat162_rn(v.z - f1.x, v.w - f1.y);
    *(__nv_bfloat162*)(hp)     = h0;
    *(__nv_bfloat162*)(hp + 2) = h1;
    *(__nv_bfloat162*)(lp)     = l0;
    *(__nv_bfloat162*)(lp + 2) = l1;
}

// fa(k, rp) / fb(k, rp): float4 of operand row (rp=0 -> block row tid>>2,
// rp=1 -> +64) at fp32 k-offset k + (tid&3)*4.
template <class FA, class FB>
__device__ __forceinline__ void gemm_core(SmemT& S, int kend, FA fa, FB fb,
                                          float (&c)[4][4][4])
{
    const int tid  = threadIdx.x;
    const int lane = tid & 31, warp = tid >> 5;
    const int wm = (warp & 1) << 6, wn = (warp >> 1) << 5;
    const int r0 = tid >> 2, r1 = r0 + 64, kq = tid & 3;

    // ldmatrix source addresses (constant across k-steps)
    const uint32_t baseA = (uint32_t)__cvta_generic_to_shared(S.Ah);
    const uint32_t baseB = (uint32_t)__cvta_generic_to_shared(S.Bh);
    uint32_t aAd[4], bAd[2];
    {
        const int arow = wm + (lane & 15), acol = (lane >> 4) << 3;
#pragma unroll
        for (int mi = 0; mi < 4; mi++)
            aAd[mi] = baseA + (uint32_t)(((arow + mi*16) * RS + acol) * 2);
        const int brow = wn + ((lane >> 4) << 3) + (lane & 7);
        const int bcol = ((lane >> 3) & 1) << 3;
#pragma unroll
        for (int p = 0; p < 2; p++)
            bAd[p] = baseB + (uint32_t)(((brow + p*16) * RS + bcol) * 2);
    }

    float4 va0 = fa(0, 0), va1 = fa(0, 1), vb0 = fb(0, 0), vb1 = fb(0, 1);

    for (int k0 = 0; k0 < kend; k0 += 16) {
        __syncthreads();
        cvt_split_store(S.Ah + r0*RS + kq*4, S.Al + r0*RS + kq*4, va0);
        cvt_split_store(S.Ah + r1*RS + kq*4, S.Al + r1*RS + kq*4, va1);
        cvt_split_store(S.Bh + r0*RS + kq*4, S.Bl + r0*RS + kq*4, vb0);
        cvt_split_store(S.Bh + r1*RS + kq*4, S.Bl + r1*RS + kq*4, vb1);
        __syncthreads();
        const int kn = k0 + 16;
        if (kn < kend) {            // prefetch next k-tile (overlaps MMA)
            va0 = fa(kn, 0); va1 = fa(kn, 1);
            vb0 = fb(kn, 0); vb1 = fb(kn, 1);
        }

        uint32_t Afh[4][4], Afl[4][4];
        uint32_t Bfh[4][2], Bfl[4][2];
#pragma unroll
        for (int mi = 0; mi < 4; mi++) {
            ldm_x4(Afh[mi], aAd[mi]);
            ldm_x4(Afl[mi], aAd[mi] + LO_OFF);
        }
#pragma unroll
        for (int p = 0; p < 2; p++) {
            uint32_t t[4];
            ldm_x4(t, bAd[p]);
            Bfh[p*2][0] = t[0]; Bfh[p*2][1] = t[1];
            Bfh[p*2+1][0] = t[2]; Bfh[p*2+1][1] = t[3];
            ldm_x4(t, bAd[p] + LO_OFF);
            Bfl[p*2][0] = t[0]; Bfl[p*2][1] = t[1];
            Bfl[p*2+1][0] = t[2]; Bfl[p*2+1][1] = t[3];
        }
#pragma unroll
        for (int mi = 0; mi < 4; mi++)
#pragma unroll
            for (int nj = 0; nj < 4; nj++) {
                mma_bf16(c[mi][nj], Afh[mi], Bfh[nj][0], Bfh[nj][1]);
                mma_bf16(c[mi][nj], Afh[mi], Bfl[nj][0], Bfl[nj][1]);
                mma_bf16(c[mi][nj], Afl[mi], Bfh[nj][0], Bfh[nj][1]);
            }
    }
}

// Fragment -> global coordinates: rows wm+mi*16+(lane>>2)(+8), cols wn+nj*8+(lane&3)*2.

// ---------------- 1) x_proj = emb[batch] @ W_ih^T + b_ih -------------------
__global__ void __launch_bounds__(256, 1) xproj_kernel(
    const int* __restrict__ batch, const float* __restrict__ emb,
    const float* __restrict__ W_ih, const float* __restrict__ b_ih)
{
    __shared__ SmemT S;
    const int m0 = blockIdx.x * 128, n0 = blockIdx.y * 128;
    const int tid = threadIdx.x, kq = tid & 3;
    const int r0 = tid >> 2, r1 = r0 + 64;

    const float* arow0 = emb + (size_t)batch[m0 + r0] * E_;
    const float* arow1 = emb + (size_t)batch[m0 + r1] * E_;
    const float* brow0 = W_ih + (size_t)(n0 + r0) * E_;
    const float* brow1 = W_ih + (size_t)(n0 + r1) * E_;

    float c[4][4][4] = {};
    gemm_core(S, E_,
        [&](int k, int rp) { return *(const float4*)((rp ? arow1 : arow0) + k + kq*4); },
        [&](int k, int rp) { return *(const float4*)((rp ? brow1 : brow0) + k + kq*4); },
        c);

    const int lane = tid & 31, warp = tid >> 5;
    const int wm = (warp & 1) << 6, wn = (warp >> 1) << 5;
    const int er = lane >> 2, ec = (lane & 3) << 1;
#pragma unroll
    for (int mi = 0; mi < 4; mi++)
#pragma unroll
        for (int nj = 0; nj < 4; nj++) {
            const int gn = n0 + wn + nj*8 + ec;
            const float2 bv = *(const float2*)(b_ih + gn);
            const int gm0 = m0 + wm + mi*16 + er;
            *(float2*)(g_xproj + (size_t)gm0 * H_ + gn) =
                make_float2(c[mi][nj][0] + bv.x, c[mi][nj][1] + bv.y);
            *(float2*)(g_xproj + (size_t)(gm0 + 8) * H_ + gn) =
                make_float2(c[mi][nj][2] + bv.x, c[mi][nj][3] + bv.y);
        }
}

// ---------------- 2) RNN: cluster of 8 CTAs per batch element --------------
__device__ __forceinline__ uint32_t ctarank() {
    uint32_t r; asm("mov.u32 %0, %%cluster_ctarank;" : "=r"(r)); return r;
}
#define RNN_CLUSTER_SYNC() do { \
    asm volatile("barrier.cluster.arrive.aligned;" ::: "memory"); \
    asm volatile("barrier.cluster.wait.aligned;"   ::: "memory"); } while (0)

__global__ void __cluster_dims__(8, 1, 1) __launch_bounds__(256, 1)
rnn_kernel(const float* __restrict__ W_hh, const float* __restrict__ b_hh)
{
    __shared__ __align__(16) float h_s[2][H_];
    const int tid  = threadIdx.x;
    const uint32_t rank = ctarank();
    const int b    = blockIdx.x >> 3;
    const int q    = tid & 3;                 // k-quarter (128 k's each)
    const int j    = rank * 64 + (tid >> 2);  // output index 0..511

    unsigned long long Wp[64];
#pragma unroll
    for (int i = 0; i < 32; i++) {
        int f4 = q*32 + ((i + 2*q) & 31);
        ulonglong2 w2 = *(const ulonglong2*)(W_hh + (size_t)j * H_ + f4 * 4);
        Wp[2*i]   = w2.x;
        Wp[2*i+1] = w2.y;
    }
    const float bias = b_hh[j];

    for (int idx = tid; idx < 2*H_; idx += 256) ((float*)h_s)[idx] = 0.0f;
    const uint32_t h_base = (uint32_t)__cvta_generic_to_shared(&h_s[0][0]);

    RNN_CLUSTER_SYNC();

    const float* xp_row = g_xproj + (size_t)b * L_ * H_ + j;
    float*       z_row  = g_z     + (size_t)b * L_ * H_ + j;

    int p = 0;
    for (int step = 0; step < L_; step++) {
        float xpv = 0.0f;
        if (q == 0) xpv = xp_row[(size_t)step * H_];

        const float* hb = p ? h_s[1] : h_s[0];
        unsigned long long c0 = 0ull, c1 = 0ull, c2 = 0ull, c3 = 0ull;
#pragma unroll
        for (int i = 0; i < 32; i += 4) {
            int f40 = q*32 + ((i + 0 + 2*q) & 31);
            int f41 = q*32 + ((i + 1 + 2*q) & 31);
            int f42 = q*32 + ((i + 2 + 2*q) & 31);
            int f43 = q*32 + ((i + 3 + 2*q) & 31);
            ulonglong2 h0 = *(const ulonglong2*)(hb + f40*4);
            ulonglong2 h1 = *(const ulonglong2*)(hb + f41*4);
            ulonglong2 h2 = *(const ulonglong2*)(hb + f42*4);
            ulonglong2 h3 = *(const ulonglong2*)(hb + f43*4);
            ffma2(c0, Wp[2*(i+0)], h0.x); ffma2(c0, Wp[2*(i+0)+1], h0.y);
            ffma2(c1, Wp[2*(i+1)], h1.x); ffma2(c1, Wp[2*(i+1)+1], h1.y);
            ffma2(c2, Wp[2*(i+2)], h2.x); ffma2(c2, Wp[2*(i+2)+1], h2.y);
            ffma2(c3, Wp[2*(i+3)], h3.x); ffma2(c3, Wp[2*(i+3)+1], h3.y);
        }
        float l0,h0f,l1,h1f,l2,h2f,l3,h3f;
        unpk(c0,l0,h0f); unpk(c1,l1,h1f); unpk(c2,l2,h2f); unpk(c3,l3,h3f);
        float acc = ((l0+h0f)+(l1+h1f)) + ((l2+h2f)+(l3+h3f));
        acc += __shfl_xor_sync(0xffffffffu, acc, 1);
        acc += __shfl_xor_sync(0xffffffffu, acc, 2);

        if (q == 0) {
            float hv = tanhf(acc + xpv + bias);
            z_row[(size_t)step * H_] = hv;
            uint32_t dst = h_base + (uint32_t)(((p ^ 1) * H_ + j) * 4);
#pragma unroll
            for (int r = 0; r < 8; r++) {
                uint32_t rad;
                asm volatile("mapa.shared::cluster.u32 %0, %1, %2;"
                             : "=r"(rad) : "r"(dst), "r"(r));
                asm volatile("st.shared::cluster.f32 [%0], %1;"
                             :: "r"(rad), "f"(hv) : "memory");
            }
        }
        RNN_CLUSTER_SYNC();
        p ^= 1;
    }
}

// ---------------- 2b) zT[b][h][l] = z[b][l][h] ------------------------------
__global__ void __launch_bounds__(256) ztrans_kernel()
{
    __shared__ float t[32][33];
    const int b  = blockIdx.z;
    const int l0 = blockIdx.x * 32, h0 = blockIdx.y * 32;
    const float* zb = g_z  + (size_t)b * L_ * H_;
    float*      ztb = g_zT + (size_t)b * H_ * L_;
    const int tx = threadIdx.x & 31, ty = threadIdx.x >> 5;   // 32 x 8
#pragma unroll
    for (int j = 0; j < 32; j += 8)
        t[ty + j][tx] = zb[(size_t)(l0 + ty + j) * H_ + h0 + tx];
    __syncthreads();
#pragma unroll
    for (int j = 0; j < 32; j += 8)
        ztb[(size_t)(h0 + ty + j) * L_ + l0 + tx] = t[tx][ty + j];
}

// ---------------- 3) scores = z @ z^T (strict lower triangle only) ---------
__global__ void __launch_bounds__(256, 1) scores_kernel()
{
    const int it = blockIdx.x, jt = blockIdx.y, b = blockIdx.z;
    if (jt > it) return;
    __shared__ SmemT S;
    const float* zb = g_z + (size_t)b * L_ * H_;
    const int l0 = it * 128, m0 = jt * 128;
    const int tid = threadIdx.x, kq = tid & 3;
    const int r0 = tid >> 2, r1 = r0 + 64;

    const float* arow0 = zb + (size_t)(l0 + r0) * H_;
    const float* arow1 = zb + (size_t)(l0 + r1) * H_;
    const float* brow0 = zb + (size_t)(m0 + r0) * H_;
    const float* brow1 = zb + (size_t)(m0 + r1) * H_;

    float c[4][4][4] = {};
    gemm_core(S, H_,
        [&](int k, int rp) { return *(const float4*)((rp ? arow1 : arow0) + k + kq*4); },
        [&](int k, int rp) { return *(const float4*)((rp ? brow1 : brow0) + k + kq*4); },
        c);

    const int lane = tid & 31, warp = tid >> 5;
    const int wm = (warp & 1) << 6, wn = (warp >> 1) << 5;
    const int er = lane >> 2, ec = (lane & 3) << 1;
    const bool full = (jt < it);
    float* sb = g_scores + (size_t)b * L_ * L_;
#pragma unroll
    for (int mi = 0; mi < 4; mi++)
#pragma unroll
        for (int nj = 0; nj < 4; nj++) {
            const int gm = m0 + wn + nj*8 + ec;
#pragma unroll
            for (int h = 0; h < 2; h++) {
                const int gl = l0 + wm + mi*16 + er + h*8;
                const float v0 = c[mi][nj][2*h], v1 = c[mi][nj][2*h+1];
                float* dst = sb + (size_t)gl * L_ + gm;
                if (full || gm + 1 < gl)      *(float2*)dst = make_float2(v0, v1);
                else if (gm < gl)             *dst = v0;
            }
        }
}

// ---------------- 4) softmax rows (in place; att semantics) ----------------
__global__ void __launch_bounds__(256) softmax_kernel()
{
    const int row = blockIdx.x;           // b*L + l
    const int l   = row & (L_ - 1);
    float* s = g_scores + (size_t)row * L_;
    const int tid = threadIdx.x;
    __shared__ float red[256];

    if (l == 0) {
        const float u = 1.0f / (float)L_;
        for (int m = tid; m < L_; m += 256) s[m] = u;
        return;
    }
    float mx = -3.402823466e38f;
    for (int m = tid; m < l; m += 256) mx = fmaxf(mx, s[m]);
    red[tid] = mx; __syncthreads();
    for (int o = 128; o; o >>= 1) {
        if (tid < o) red[tid] = fmaxf(red[tid], red[tid + o]);
        __syncthreads();
    }
    mx = red[0]; __syncthreads();

    float sum = 0.0f;
    for (int m = tid; m < l; m += 256) {
        float e = expf(s[m] - mx);
        s[m] = e;
        sum += e;
    }
    red[tid] = sum; __syncthreads();
    for (int o = 128; o; o >>= 1) {
        if (tid < o) red[tid] += red[tid + o];
        __syncthreads();
    }
    const float inv = 1.0f / red[0];
    for (int m = tid; m < l; m += 256) s[m] *= inv;
    for (int m = l + tid; m < L_; m += 256) s[m] = 0.0f;
}

// ---------------- 5) att_vec = att @ z  (B from zT; per-tile K limit) ------
__global__ void __launch_bounds__(256, 1) attv_kernel()
{
    const int it = blockIdx.x, nt = blockIdx.y, b = blockIdx.z;
    __shared__ SmemT S;
    const int l0 = it * 128, n0 = nt * 128;
    const float* ab  = g_scores + (size_t)b * L_ * L_;
    const int tid = threadIdx.x, kq = tid & 3;
    const int r0 = tid >> 2, r1 = r0 + 64;

    const float* arow0 = ab + (size_t)(l0 + r0) * L_;
    const float* arow1 = ab + (size_t)(l0 + r1) * L_;
    const float* brow0 = g_zT + ((size_t)b * H_ + n0 + r0) * L_;
    const float* brow1 = g_zT + ((size_t)b * H_ + n0 + r1) * L_;
    // tile 0 contains uniform row 0 -> full K; others: k <= tile end (rest zeros)
    const int kend = (it == 0) ? L_ : (it + 1) * 128;

    float c[4][4][4] = {};
    gemm_core(S, kend,
        [&](int k, int rp) { return *(const float4*)((rp ? arow1 : arow0) + k + kq*4); },
        [&](int k, int rp) { return *(const float4*)((rp ? brow1 : brow0) + k + kq*4); },
        c);

    const int lane = tid & 31, warp = tid >> 5;
    const int wm = (warp & 1) << 6, wn = (warp >> 1) << 5;
    const int er = lane >> 2, ec = (lane & 3) << 1;
#pragma unroll
    for (int mi = 0; mi < 4; mi++)
#pragma unroll
        for (int nj = 0; nj < 4; nj++) {
            const int gn = n0 + wn + nj*8 + ec;
            const int gl0 = l0 + wm + mi*16 + er;
            *(float2*)(g_attv + ((size_t)b * L_ + gl0) * H_ + gn) =
                make_float2(c[mi][nj][0], c[mi][nj][1]);
            *(float2*)(g_attv + ((size_t)b * L_ + gl0 + 8) * H_ + gn) =
                make_float2(c[mi][nj][2], c[mi][nj][3]);
        }
}

// ---------------- 6) dec_in = [att_vec, z] @ W_c^T + b_c -------------------
__global__ void __launch_bounds__(256, 1) decin_kernel(
    const float* __restrict__ W_c, const float* __restrict__ b_c)
{
    __shared__ SmemT S;
    const int m0 = blockIdx.x * 128, n0 = blockIdx.y * 128;
    const int tid = threadIdx.x, kq = tid & 3;
    const int r0 = tid >> 2, r1 = r0 + 64;

    const float* a0att = g_attv + (size_t)(m0 + r0) * H_;
    const float* a1att = g_attv + (size_t)(m0 + r1) * H_;
    const float* a0z   = g_z    + (size_t)(m0 + r0) * H_;
    const float* a1z   = g_z    + (size_t)(m0 + r1) * H_;
    const float* brow0 = W_c + (size_t)(n0 + r0) * (2*H_);
    const float* brow1 = W_c + (size_t)(n0 + r1) * (2*H_);

    float c[4][4][4] = {};
    gemm_core(S, 2*H_,
        [&](int k, int rp) {
            const float* base = (k < H_) ? (rp ? a1att : a0att) + k
                                         : (rp ? a1z : a0z) + (k - H_);
            return *(const float4*)(base + kq*4);
        },
        [&](int k, int rp) { return *(const float4*)((rp ? brow1 : brow0) + k + kq*4); },
        c);

    const int lane = tid & 31, warp = tid >> 5;
    const int wm = (warp & 1) << 6, wn = (warp >> 1) << 5;
    const int er = lane >> 2, ec = (lane & 3) << 1;
#pragma unroll
    for (int mi = 0; mi < 4; mi++)
#pragma unroll
        for (int nj = 0; nj < 4; nj++) {
            const int gn = n0 + wn + nj*8 + ec;
            const float2 bv = *(const float2*)(b_c + gn);
            const int gm0 = m0 + wm + mi*16 + er;
            *(float2*)(g_decin + (size_t)gm0 * H_ + gn) =
                make_float2(c[mi][nj][0] + bv.x, c[mi][nj][1] + bv.y);
            *(float2*)(g_decin + (size_t)(gm0 + 8) * H_ + gn) =
                make_float2(c[mi][nj][2] + bv.x, c[mi][nj][3] + bv.y);
        }
}

// ---------------- 7) logits = dec_in @ W_d^T + b_d -------------------------
__global__ void __launch_bounds__(256, 1) logits_kernel(
    const float* __restrict__ W_d, const float* __restrict__ b_d,
    float* __restrict__ out)
{
    __shared__ SmemT S;
    const int m0 = blockIdx.x * 128, n0 = blockIdx.y * 128;
    const int tid = threadIdx.x, kq = tid & 3;
    const int r0 = tid >> 2, r1 = r0 + 64;

    const float* arow0 = g_decin + (size_t)(m0 + r0) * H_;
    const float* arow1 = g_decin + (size_t)(m0 + r1) * H_;
    const int nrow0 = n0 + r0, nrow1 = n0 + r1;
    const bool v0 = nrow0 < V_, v1 = nrow1 < V_;
    const float* brow0 = W_d + (size_t)(v0 ? nrow0 : 0) * H_;
    const float* brow1 = W_d + (size_t)(v1 ? nrow1 : 0) * H_;

    float c[4][4][4] = {};
    gemm_core(S, H_,
        [&](int k, int rp) { return *(const float4*)((rp ? arow1 : arow0) + k + kq*4); },
        [&](int k, int rp) {
            const bool ok = rp ? v1 : v0;
            if (!ok) return make_float4(0.f, 0.f, 0.f, 0.f);
            return *(const float4*)((rp ? brow1 : brow0) + k + kq*4);
        },
        c);

    const int lane = tid & 31, warp = tid >> 5;
    const int wm = (warp & 1) << 6, wn = (warp >> 1) << 5;
    const int er = lane >> 2, ec = (lane & 3) << 1;
#pragma unroll
    for (int mi = 0; mi < 4; mi++)
#pragma unroll
        for (int nj = 0; nj < 4; nj++) {
            const int gn = n0 + wn + nj*8 + ec;
            if (gn < V_) {                           // V_ even, gn even
                const float2 bv = *(const float2*)(b_d + gn);
                const int gm0 = m0 + wm + mi*16 + er;
                *(float2*)(out + (size_t)gm0 * V_ + gn) =
                    make_float2(c[mi][nj][0] + bv.x, c[mi][nj][1] + bv.y);
                *(float2*)(out + (size_t)(gm0 + 8) * V_ + gn) =
                    make_float2(c[mi][nj][2] + bv.x, c[mi][nj][3] + bv.y);
            }
        }
}

// ---------------- launch ----------------------------------------------------
extern "C" void kernel_launch(void* const* d_in, const int* in_sizes, int n_in,
                              void* d_out, int out_size)
{
    const int*   batch = (const int*)  d_in[0];
    const float* emb   = (const float*)d_in[1];
    const float* W_ih  = (const float*)d_in[2];
    const float* b_ih  = (const float*)d_in[3];
    const float* W_hh  = (const float*)d_in[4];
    const float* b_hh  = (const float*)d_in[5];
    const float* W_c   = (const float*)d_in[6];
    const float* b_c   = (const float*)d_in[7];
    const float* W_d   = (const float*)d_in[8];
    const float* b_d   = (const float*)d_in[9];
    float* out = (float*)d_out;
    (void)in_sizes; (void)n_in; (void)out_size;

    xproj_kernel  <<<dim3(ML/128, H_/128), 256>>>(batch, emb, W_ih, b_ih);
    rnn_kernel    <<<dim3(B_*8), 256>>>(W_hh, b_hh);          // 8 clusters of 8 CTAs
    ztrans_kernel <<<dim3(L_/32, H_/32, B_), 256>>>();
    scores_kernel <<<dim3(L_/128, L_/128, B_), 256>>>();
    softmax_kernel<<<dim3(ML), 256>>>();
    attv_kernel   <<<dim3(L_/128, H_/128, B_), 256>>>();
    decin_kernel  <<<dim3(ML/128, H_/128), 256>>>(W_c, b_c);
    logits_kernel <<<dim3(ML/128, (V_ + 127)/128), 256>>>(W_d, b_d, out);
}